// round 1
// baseline (speedup 1.0000x reference)
#include <cuda_runtime.h>
#include <cstdio>

#define BATCH 2
#define NPTS  4096
#define KNN   20
#define BN_   (BATCH*NPTS)        // 8192
#define CNT_EDGE (float)(BATCH*NPTS*KNN)   // 163840
#define EPSV 1e-5f
#define SLOPE 0.2f

// ---------------- static scratch (no runtime alloc allowed) ----------------
__device__ float g_xb[BN_*3];
__device__ float g_x1[BN_*64];
__device__ float g_x2[BN_*64];
__device__ float g_x3[BN_*128];
__device__ float g_x4[BN_*256];
__device__ float g_sq[BN_];
__device__ float g_D[(size_t)BATCH*NPTS*NPTS];   // 134MB distance scratch
__device__ int   g_idx[BN_*KNN];
__device__ float g_u[BN_*256];
__device__ float g_v[BN_*256];
__device__ float g_wdiff[256*256];
__device__ float g_cat[BN_*512];
__device__ float g_h[(size_t)BN_*1024];
__device__ float g_ps [(size_t)BN_*256];  // partial sums
__device__ float g_pss[(size_t)BN_*256];  // partial sumsq
__device__ float g_sums[1024];
__device__ float g_sumsq[1024];

// ---------------- kernels ----------------

// x (B,3,N) -> g_xb (B,N,3)
__global__ void k_transpose_x(const float* __restrict__ x) {
    int i = blockIdx.x*blockDim.x + threadIdx.x;
    if (i >= BN_) return;
    int b = i / NPTS, n = i % NPTS;
    #pragma unroll
    for (int c = 0; c < 3; c++)
        g_xb[(size_t)i*3 + c] = x[((size_t)b*3 + c)*NPTS + n];
}

// squared norms per row
__global__ void k_sqnorm(const float* __restrict__ F, int C) {
    int i = blockIdx.x*blockDim.x + threadIdx.x;
    if (i >= BN_) return;
    const float* r = F + (size_t)i*C;
    float s = 0.f;
    for (int c = 0; c < C; c++) s += r[c]*r[c];
    g_sq[i] = s;
}

// D[b][n][m] = 2*<x_n,x_m> - ||x_n||^2 - ||x_m||^2   (64x64 tile, 4x4 micro)
__global__ void k_dist(const float* __restrict__ F, int C) {
    int b = blockIdx.z;
    const float* Fb = F + (size_t)b*NPTS*C;
    int m0 = blockIdx.x*64, n0 = blockIdx.y*64;
    __shared__ float As[16][68];  // As[k][n-row]
    __shared__ float Bs[16][68];  // Bs[k][m-row]
    int tid = threadIdx.x;
    float acc[4][4];
    #pragma unroll
    for (int i = 0; i < 4; i++)
        #pragma unroll
        for (int j = 0; j < 4; j++) acc[i][j] = 0.f;

    for (int c0 = 0; c0 < C; c0 += 16) {
        int r = tid >> 4, c = tid & 15;
        #pragma unroll
        for (int it = 0; it < 4; it++) {
            int row = r + it*16;
            int cc = c0 + c;
            As[c][row] = (cc < C) ? Fb[(size_t)(n0+row)*C + cc] : 0.f;
            Bs[c][row] = (cc < C) ? Fb[(size_t)(m0+row)*C + cc] : 0.f;
        }
        __syncthreads();
        int ti = tid & 15, tj = tid >> 4;   // ti -> m (fast), tj -> n
        #pragma unroll
        for (int k = 0; k < 16; k++) {
            float a[4], bv[4];
            #pragma unroll
            for (int u = 0; u < 4; u++) { a[u] = As[k][tj*4+u]; bv[u] = Bs[k][ti*4+u]; }
            #pragma unroll
            for (int i = 0; i < 4; i++)
                #pragma unroll
                for (int j = 0; j < 4; j++) acc[i][j] += a[i]*bv[j];
        }
        __syncthreads();
    }
    int ti = tid & 15, tj = tid >> 4;
    #pragma unroll
    for (int i = 0; i < 4; i++) {
        int n = n0 + tj*4 + i;
        float sqn = g_sq[b*NPTS + n];
        float4 v;
        v.x = 2.f*acc[i][0] - sqn - g_sq[b*NPTS + m0+ti*4+0];
        v.y = 2.f*acc[i][1] - sqn - g_sq[b*NPTS + m0+ti*4+1];
        v.z = 2.f*acc[i][2] - sqn - g_sq[b*NPTS + m0+ti*4+2];
        v.w = 2.f*acc[i][3] - sqn - g_sq[b*NPTS + m0+ti*4+3];
        *(float4*)&g_D[((size_t)b*NPTS + n)*NPTS + m0 + ti*4] = v;
    }
}

// top-20 (largest values, tie -> lowest index) per distance row
__global__ void k_topk() {
    __shared__ float vals[NPTS];
    __shared__ float rv[256];
    __shared__ int   ri[256];
    int bn = blockIdx.x;
    const float* row = &g_D[(size_t)bn*NPTS];
    for (int i = threadIdx.x; i < NPTS; i += 256) vals[i] = row[i];
    __syncthreads();
    for (int it = 0; it < KNN; it++) {
        float bestv = -3.4e38f; int besti = 1 << 30;
        for (int i = threadIdx.x; i < NPTS; i += 256) {
            float v = vals[i];
            if (v > bestv || (v == bestv && i < besti)) { bestv = v; besti = i; }
        }
        rv[threadIdx.x] = bestv; ri[threadIdx.x] = besti;
        __syncthreads();
        for (int s = 128; s > 0; s >>= 1) {
            if (threadIdx.x < s) {
                float v2 = rv[threadIdx.x+s]; int i2 = ri[threadIdx.x+s];
                float v1 = rv[threadIdx.x];   int i1 = ri[threadIdx.x];
                if (v2 > v1 || (v2 == v1 && i2 < i1)) { rv[threadIdx.x] = v2; ri[threadIdx.x] = i2; }
            }
            __syncthreads();
        }
        if (threadIdx.x == 0) {
            g_idx[bn*KNN + it] = ri[0];
            vals[ri[0]] = -3.4e38f;
        }
        __syncthreads();
    }
}

// wdiff[o][c] = W[o][C+c] - W[o][c]   (W is O x 2C)
__global__ void k_wdiff(const float* __restrict__ W, int O, int C) {
    int i = blockIdx.x*blockDim.x + threadIdx.x;
    if (i >= O*C) return;
    int o = i / C, c = i % C;
    g_wdiff[i] = W[(size_t)o*2*C + C + c] - W[(size_t)o*2*C + c];
}

// Out[M][O] = A[M][Kd] * W[O][ldw]^T (use first Kd cols of each W row)
__global__ void k_gemm(const float* __restrict__ A, const float* __restrict__ W,
                       float* __restrict__ Out, int O, int Kd, int ldw) {
    int m0 = blockIdx.y*64, o0 = blockIdx.x*64;
    __shared__ float As[16][68];
    __shared__ float Ws[16][68];
    int tid = threadIdx.x;
    float acc[4][4];
    #pragma unroll
    for (int i = 0; i < 4; i++)
        #pragma unroll
        for (int j = 0; j < 4; j++) acc[i][j] = 0.f;

    for (int k0 = 0; k0 < Kd; k0 += 16) {
        int r = tid >> 4, c = tid & 15;
        #pragma unroll
        for (int it = 0; it < 4; it++) {
            int row = r + it*16;
            int kk = k0 + c;
            As[c][row] = (kk < Kd) ? A[(size_t)(m0+row)*Kd + kk] : 0.f;
            Ws[c][row] = (kk < Kd) ? W[(size_t)(o0+row)*ldw + kk] : 0.f;
        }
        __syncthreads();
        int ti = tid & 15, tj = tid >> 4;   // ti -> o (fast), tj -> m
        #pragma unroll
        for (int k = 0; k < 16; k++) {
            float a[4], w[4];
            #pragma unroll
            for (int u = 0; u < 4; u++) { a[u] = As[k][tj*4+u]; w[u] = Ws[k][ti*4+u]; }
            #pragma unroll
            for (int i = 0; i < 4; i++)
                #pragma unroll
                for (int j = 0; j < 4; j++) acc[i][j] += a[i]*w[j];
        }
        __syncthreads();
    }
    int ti = tid & 15, tj = tid >> 4;
    #pragma unroll
    for (int i = 0; i < 4; i++) {
        int m = m0 + tj*4 + i;
        float4 v = make_float4(acc[i][0], acc[i][1], acc[i][2], acc[i][3]);
        *(float4*)&Out[(size_t)m*O + o0 + ti*4] = v;
    }
}

// per (b,n): pre[o] = v[o] + max_k u[idx_k][o]; partial per-channel sum/sumsq
__global__ void k_gather(int O, float* __restrict__ pre) {
    int bn = blockIdx.x;
    int b = bn >> 12;
    __shared__ int nb[KNN];
    if (threadIdx.x < KNN) nb[threadIdx.x] = g_idx[bn*KNN + threadIdx.x];
    __syncthreads();
    int o = threadIdx.x;
    float vv = g_v[(size_t)bn*O + o];
    float mx = -3.4e38f, s = 0.f, ss = 0.f;
    #pragma unroll
    for (int k = 0; k < KNN; k++) {
        float h = g_u[((size_t)(b*NPTS + nb[k]))*O + o] + vv;
        mx = fmaxf(mx, h); s += h; ss += h*h;
    }
    pre[(size_t)bn*O + o] = mx;
    g_ps [(size_t)bn*O + o] = s;
    g_pss[(size_t)bn*O + o] = ss;
}

// deterministic reduction of partials -> g_sums/g_sumsq
__global__ void k_redstats(int nPart, int O) {
    int o = blockIdx.x, tid = threadIdx.x;
    float s = 0.f, ss = 0.f;
    for (int i = tid; i < nPart; i += 256) {
        s  += g_ps [(size_t)i*O + o];
        ss += g_pss[(size_t)i*O + o];
    }
    __shared__ float rs[256], rss[256];
    rs[tid] = s; rss[tid] = ss;
    __syncthreads();
    for (int st = 128; st > 0; st >>= 1) {
        if (tid < st) { rs[tid] += rs[tid+st]; rss[tid] += rss[tid+st]; }
        __syncthreads();
    }
    if (tid == 0) { g_sums[o] = rs[0]; g_sumsq[o] = rss[0]; }
}

// in-place affine-BN + leaky on max-pooled features
__global__ void k_finalize(const float* __restrict__ g, const float* __restrict__ bp,
                           float* __restrict__ buf, int O, float invCnt) {
    int i = blockIdx.x*blockDim.x + threadIdx.x;
    if (i >= BN_*O) return;
    int o = i % O;
    float mean = g_sums[o]*invCnt;
    float var  = g_sumsq[o]*invCnt - mean*mean;
    float sc = g[o]*rsqrtf(var + EPSV);
    float sh = bp[o] - mean*sc;
    float y = sc*buf[i] + sh;
    buf[i] = (y > 0.f) ? y : SLOPE*y;
}

__global__ void k_concat() {
    int i = blockIdx.x*blockDim.x + threadIdx.x;
    if (i >= BN_*512) return;
    int m = i / 512, c = i % 512;
    float v;
    if (c < 64)       v = g_x1[(size_t)m*64  + c];
    else if (c < 128) v = g_x2[(size_t)m*64  + c-64];
    else if (c < 256) v = g_x3[(size_t)m*128 + c-128];
    else              v = g_x4[(size_t)m*256 + c-256];
    g_cat[i] = v;
}

// partial per-channel stats of g_h (8192 x 1024): 256 blocks x 32 rows
__global__ void k_hstats() {
    int r0 = blockIdx.x*32;
    float s[4] = {0,0,0,0}, ss[4] = {0,0,0,0};
    for (int r = 0; r < 32; r++) {
        const float* row = &g_h[(size_t)(r0+r)*1024];
        #pragma unroll
        for (int q = 0; q < 4; q++) {
            float v = row[threadIdx.x + q*256];
            s[q] += v; ss[q] += v*v;
        }
    }
    #pragma unroll
    for (int q = 0; q < 4; q++) {
        g_ps [(size_t)blockIdx.x*1024 + threadIdx.x + q*256] = s[q];
        g_pss[(size_t)blockIdx.x*1024 + threadIdx.x + q*256] = ss[q];
    }
}

// BN + leaky + transpose: out[b][o][n]
__global__ void k_out(const float* __restrict__ g5, const float* __restrict__ b5,
                      float* __restrict__ out) {
    __shared__ float t[32][33];
    int b = blockIdx.z;
    int n0 = blockIdx.x*32, o0 = blockIdx.y*32;
    for (int dy = threadIdx.y; dy < 32; dy += 8) {
        int n = n0 + dy;
        t[dy][threadIdx.x] = g_h[(size_t)(b*NPTS + n)*1024 + o0 + threadIdx.x];
    }
    __syncthreads();
    const float invCnt = 1.f/8192.f;
    for (int dy = threadIdx.y; dy < 32; dy += 8) {
        int o = o0 + dy, n = n0 + threadIdx.x;
        float mean = g_sums[o]*invCnt;
        float var  = g_sumsq[o]*invCnt - mean*mean;
        float sc = g5[o]*rsqrtf(var + EPSV);
        float sh = b5[o] - mean*sc;
        float hv = t[threadIdx.x][dy];
        float y = sc*hv + sh;
        out[((size_t)b*1024 + o)*NPTS + n] = (y > 0.f) ? y : SLOPE*y;
    }
}

// ---------------- host launch ----------------

static void run_layer(const float* F, int C, const float* W, const float* g,
                      const float* bp, int O, float* outbuf,
                      float* p_u, float* p_v, float* p_wdiff) {
    k_sqnorm<<<(BN_+255)/256, 256>>>(F, C);
    k_dist<<<dim3(64, 64, BATCH), 256>>>(F, C);
    k_topk<<<BN_, 256>>>();
    k_wdiff<<<(O*C + 255)/256, 256>>>(W, O, C);
    k_gemm<<<dim3(O/64, BN_/64), 256>>>(F, W,       p_u, O, C, 2*C);  // u = Wa * x
    k_gemm<<<dim3(O/64, BN_/64), 256>>>(F, p_wdiff, p_v, O, C, C);    // v = (Wb-Wa)*x
    k_gather<<<BN_, O>>>(O, outbuf);
    k_redstats<<<O, 256>>>(BN_, O);
    k_finalize<<<(BN_*O + 255)/256, 256>>>(g, bp, outbuf, O, 1.f/CNT_EDGE);
}

extern "C" void kernel_launch(void* const* d_in, const int* in_sizes, int n_in,
                              void* d_out, int out_size) {
    const float* x  = (const float*)d_in[0];
    const float* W1 = (const float*)d_in[1];
    const float* g1 = (const float*)d_in[2];
    const float* b1 = (const float*)d_in[3];
    const float* W2 = (const float*)d_in[4];
    const float* g2 = (const float*)d_in[5];
    const float* b2 = (const float*)d_in[6];
    const float* W3 = (const float*)d_in[7];
    const float* g3 = (const float*)d_in[8];
    const float* b3 = (const float*)d_in[9];
    const float* W4 = (const float*)d_in[10];
    const float* g4 = (const float*)d_in[11];
    const float* b4 = (const float*)d_in[12];
    const float* W5 = (const float*)d_in[13];
    const float* g5 = (const float*)d_in[14];
    const float* b5 = (const float*)d_in[15];
    float* out = (float*)d_out;

    float *p_xb, *p_x1, *p_x2, *p_x3, *p_x4, *p_u, *p_v, *p_wdiff, *p_cat, *p_h;
    cudaGetSymbolAddress((void**)&p_xb,    g_xb);
    cudaGetSymbolAddress((void**)&p_x1,    g_x1);
    cudaGetSymbolAddress((void**)&p_x2,    g_x2);
    cudaGetSymbolAddress((void**)&p_x3,    g_x3);
    cudaGetSymbolAddress((void**)&p_x4,    g_x4);
    cudaGetSymbolAddress((void**)&p_u,     g_u);
    cudaGetSymbolAddress((void**)&p_v,     g_v);
    cudaGetSymbolAddress((void**)&p_wdiff, g_wdiff);
    cudaGetSymbolAddress((void**)&p_cat,   g_cat);
    cudaGetSymbolAddress((void**)&p_h,     g_h);

    k_transpose_x<<<(BN_+255)/256, 256>>>(x);

    run_layer(p_xb, 3,   W1, g1, b1, 64,  p_x1, p_u, p_v, p_wdiff);
    run_layer(p_x1, 64,  W2, g2, b2, 64,  p_x2, p_u, p_v, p_wdiff);
    run_layer(p_x2, 64,  W3, g3, b3, 128, p_x3, p_u, p_v, p_wdiff);
    run_layer(p_x3, 128, W4, g4, b4, 256, p_x4, p_u, p_v, p_wdiff);

    k_concat<<<(BN_*512 + 255)/256, 256>>>();
    k_gemm<<<dim3(1024/64, BN_/64), 256>>>(p_cat, W5, p_h, 1024, 512, 512);
    k_hstats<<<256, 256>>>();
    k_redstats<<<1024, 256>>>(256, 1024);
    k_out<<<dim3(NPTS/32, 1024/32, BATCH), dim3(32, 8)>>>(g5, b5, out);
}

// round 2
// speedup vs baseline: 1.4631x; 1.4631x over previous
#include <cuda_runtime.h>
#include <cstdio>

#define BATCH 2
#define NPTS  4096
#define KNN   20
#define BN_   (BATCH*NPTS)        // 8192
#define CNT_EDGE (float)(BATCH*NPTS*KNN)   // 163840
#define EPSV 1e-5f
#define SLOPE 0.2f
#define TOPK_CAP 1024

// ---------------- static scratch (no runtime alloc allowed) ----------------
__device__ float g_xb[BN_*3];
__device__ float g_x1[BN_*64];
__device__ float g_x2[BN_*64];
__device__ float g_x3[BN_*128];
__device__ float g_x4[BN_*256];
__device__ float g_sq[BN_];
__device__ float g_D[(size_t)BATCH*NPTS*NPTS];   // 134MB distance scratch
__device__ int   g_idx[BN_*KNN];
__device__ float g_u[BN_*256];
__device__ float g_v[BN_*256];
__device__ float g_wdiff[256*256];
__device__ float g_cat[BN_*512];
__device__ float g_h[(size_t)BN_*1024];
__device__ float g_ps [(size_t)BN_*256];  // partial sums
__device__ float g_pss[(size_t)BN_*256];  // partial sumsq
__device__ float g_sums[1024];
__device__ float g_sumsq[1024];

// ---------------- kernels ----------------

// x (B,3,N) -> g_xb (B,N,3)
__global__ void k_transpose_x(const float* __restrict__ x) {
    int i = blockIdx.x*blockDim.x + threadIdx.x;
    if (i >= BN_) return;
    int b = i / NPTS, n = i % NPTS;
    #pragma unroll
    for (int c = 0; c < 3; c++)
        g_xb[(size_t)i*3 + c] = x[((size_t)b*3 + c)*NPTS + n];
}

// squared norms per row
__global__ void k_sqnorm(const float* __restrict__ F, int C) {
    int i = blockIdx.x*blockDim.x + threadIdx.x;
    if (i >= BN_) return;
    const float* r = F + (size_t)i*C;
    float s = 0.f;
    for (int c = 0; c < C; c++) s += r[c]*r[c];
    g_sq[i] = s;
}

// D[b][n][m] = 2*<x_n,x_m> - ||x_n||^2 - ||x_m||^2
// 128x128 tile, 8x8 micro, 256 threads
__global__ void k_dist128(const float* __restrict__ F, int C) {
    int b = blockIdx.z;
    const float* Fb = F + (size_t)b*NPTS*C;
    int m0 = blockIdx.x*128, n0 = blockIdx.y*128;
    __shared__ float As[8][132];  // As[k][n-row]
    __shared__ float Bs[8][132];  // Bs[k][m-row]
    int tid = threadIdx.x;
    float acc[8][8];
    #pragma unroll
    for (int i = 0; i < 8; i++)
        #pragma unroll
        for (int j = 0; j < 8; j++) acc[i][j] = 0.f;

    int lr = tid & 127;          // row within tile
    int lk = (tid >> 7) * 4;     // starting k (0 or 4)

    for (int c0 = 0; c0 < C; c0 += 8) {
        #pragma unroll
        for (int q = 0; q < 4; q++) {
            int cc = c0 + lk + q;
            As[lk+q][lr] = (cc < C) ? Fb[(size_t)(n0+lr)*C + cc] : 0.f;
            Bs[lk+q][lr] = (cc < C) ? Fb[(size_t)(m0+lr)*C + cc] : 0.f;
        }
        __syncthreads();
        int ti = tid & 15, tj = tid >> 4;   // ti -> m (fast), tj -> n
        #pragma unroll
        for (int k = 0; k < 8; k++) {
            float a[8], bv[8];
            #pragma unroll
            for (int u = 0; u < 8; u++) { a[u] = As[k][tj*8+u]; bv[u] = Bs[k][ti*8+u]; }
            #pragma unroll
            for (int i = 0; i < 8; i++)
                #pragma unroll
                for (int j = 0; j < 8; j++) acc[i][j] += a[i]*bv[j];
        }
        __syncthreads();
    }
    int ti = tid & 15, tj = tid >> 4;
    float sqm[8];
    #pragma unroll
    for (int j = 0; j < 8; j++) sqm[j] = g_sq[b*NPTS + m0 + ti*8 + j];
    #pragma unroll
    for (int i = 0; i < 8; i++) {
        int n = n0 + tj*8 + i;
        float sqn = g_sq[b*NPTS + n];
        float* orow = &g_D[((size_t)b*NPTS + n)*NPTS + m0 + ti*8];
        float4 v0, v1;
        v0.x = 2.f*acc[i][0] - sqn - sqm[0];
        v0.y = 2.f*acc[i][1] - sqn - sqm[1];
        v0.z = 2.f*acc[i][2] - sqn - sqm[2];
        v0.w = 2.f*acc[i][3] - sqn - sqm[3];
        v1.x = 2.f*acc[i][4] - sqn - sqm[4];
        v1.y = 2.f*acc[i][5] - sqn - sqm[5];
        v1.z = 2.f*acc[i][6] - sqn - sqm[6];
        v1.w = 2.f*acc[i][7] - sqn - sqm[7];
        *(float4*)&orow[0] = v0;
        *(float4*)&orow[4] = v1;
    }
}

__device__ __forceinline__ unsigned f2ord(float f) {
    unsigned u = __float_as_uint(f);
    return (u & 0x80000000u) ? ~u : (u | 0x80000000u);
}

// top-20 (largest values, tie -> lowest index) per distance row.
// Radix-select: single global pass, 11-bit histogram, candidate ranking.
__global__ void k_topk() {
    __shared__ unsigned hist[2048];
    __shared__ unsigned tsum[256];
    __shared__ int sh_bin, sh_above, ccnt;
    __shared__ unsigned long long cand[TOPK_CAP];

    int bn = blockIdx.x;
    int tid = threadIdx.x;
    const float4* rowv = (const float4*)&g_D[(size_t)bn*NPTS];

    for (int i = tid; i < 2048; i += 256) hist[i] = 0;
    if (tid == 0) ccnt = 0;
    __syncthreads();

    // load 16 values/thread, compute ordered keys, histogram top-11 bits
    unsigned ord[16];
    #pragma unroll
    for (int q = 0; q < 4; q++) {
        float4 v = rowv[tid + q*256];
        ord[q*4+0] = f2ord(v.x);
        ord[q*4+1] = f2ord(v.y);
        ord[q*4+2] = f2ord(v.z);
        ord[q*4+3] = f2ord(v.w);
    }
    #pragma unroll
    for (int q = 0; q < 16; q++) atomicAdd(&hist[ord[q] >> 21], 1u);
    __syncthreads();

    // per-thread sum over its 8 bins, then suffix-scan across threads
    unsigned s_local = 0;
    #pragma unroll
    for (int j = 0; j < 8; j++) s_local += hist[tid*8 + j];
    tsum[tid] = s_local;
    __syncthreads();
    for (int off = 1; off < 256; off <<= 1) {
        unsigned add = (tid + off < 256) ? tsum[tid + off] : 0u;
        __syncthreads();
        tsum[tid] += add;
        __syncthreads();
    }
    // tsum[tid] = sum over bins of threads >= tid
    unsigned cum = tsum[tid] - s_local;   // count strictly above this thread's bin range
    for (int j = 7; j >= 0; j--) {
        unsigned c = hist[tid*8 + j];
        if (cum < KNN && cum + c >= KNN) { sh_bin = tid*8 + j; sh_above = (int)cum; }
        cum += c;
    }
    __syncthreads();

    int thr = sh_bin;
    // collect candidates: all elements with bin >= threshold bin
    #pragma unroll
    for (int q = 0; q < 16; q++) {
        if ((int)(ord[q] >> 21) >= thr) {
            int idx = 4*(tid + (q >> 2)*256) + (q & 3);
            int p = atomicAdd(&ccnt, 1);
            if (p < TOPK_CAP)
                cand[p] = ((unsigned long long)ord[q] << 32) | (unsigned)(NPTS - 1 - idx);
        }
    }
    __syncthreads();

    int T = ccnt;
    if (T <= TOPK_CAP) {
        // rank candidates; keys are unique (index embedded) -> deterministic
        for (int i = tid; i < T; i += 256) {
            unsigned long long ki = cand[i];
            int r = 0;
            for (int j = 0; j < T; j++) r += (cand[j] > ki);
            if (r < KNN) {
                int idx = (NPTS - 1) - (int)(unsigned)(ki & 0xFFFFFFFFull);
                g_idx[bn*KNN + r] = idx;
            }
        }
    } else {
        // fallback (degenerate): iterative in-register selection, always correct
        __shared__ unsigned long long rb[256];
        unsigned mask = 0xFFFFu;
        for (int it = 0; it < KNN; it++) {
            unsigned long long best = 0ull;
            #pragma unroll
            for (int q = 0; q < 16; q++) {
                if ((mask >> q) & 1u) {
                    int idx = 4*(tid + (q >> 2)*256) + (q & 3);
                    unsigned long long k = ((unsigned long long)ord[q] << 32)
                                         | (unsigned)(NPTS - 1 - idx);
                    if (k > best) best = k;
                }
            }
            rb[tid] = best;
            __syncthreads();
            for (int st = 128; st > 0; st >>= 1) {
                if (tid < st && rb[tid + st] > rb[tid]) rb[tid] = rb[tid + st];
                __syncthreads();
            }
            unsigned long long win = rb[0];
            if (tid == 0)
                g_idx[bn*KNN + it] = (NPTS - 1) - (int)(unsigned)(win & 0xFFFFFFFFull);
            // owner clears its bit
            #pragma unroll
            for (int q = 0; q < 16; q++) {
                if ((mask >> q) & 1u) {
                    int idx = 4*(tid + (q >> 2)*256) + (q & 3);
                    unsigned long long k = ((unsigned long long)ord[q] << 32)
                                         | (unsigned)(NPTS - 1 - idx);
                    if (k == win) mask &= ~(1u << q);
                }
            }
            __syncthreads();
        }
    }
}

// wdiff[o][c] = W[o][C+c] - W[o][c]   (W is O x 2C)
__global__ void k_wdiff(const float* __restrict__ W, int O, int C) {
    int i = blockIdx.x*blockDim.x + threadIdx.x;
    if (i >= O*C) return;
    int o = i / C, c = i % C;
    g_wdiff[i] = W[(size_t)o*2*C + C + c] - W[(size_t)o*2*C + c];
}

// Out[M][O] = A[M][Kd] * W[O][ldw]^T  (64x64 tile; used for small point GEMMs)
__global__ void k_gemm(const float* __restrict__ A, const float* __restrict__ W,
                       float* __restrict__ Out, int O, int Kd, int ldw) {
    int m0 = blockIdx.y*64, o0 = blockIdx.x*64;
    __shared__ float As[16][68];
    __shared__ float Ws[16][68];
    int tid = threadIdx.x;
    float acc[4][4];
    #pragma unroll
    for (int i = 0; i < 4; i++)
        #pragma unroll
        for (int j = 0; j < 4; j++) acc[i][j] = 0.f;

    for (int k0 = 0; k0 < Kd; k0 += 16) {
        int r = tid >> 4, c = tid & 15;
        #pragma unroll
        for (int it = 0; it < 4; it++) {
            int row = r + it*16;
            int kk = k0 + c;
            As[c][row] = (kk < Kd) ? A[(size_t)(m0+row)*Kd + kk] : 0.f;
            Ws[c][row] = (kk < Kd) ? W[(size_t)(o0+row)*ldw + kk] : 0.f;
        }
        __syncthreads();
        int ti = tid & 15, tj = tid >> 4;
        #pragma unroll
        for (int k = 0; k < 16; k++) {
            float a[4], w[4];
            #pragma unroll
            for (int u = 0; u < 4; u++) { a[u] = As[k][tj*4+u]; w[u] = Ws[k][ti*4+u]; }
            #pragma unroll
            for (int i = 0; i < 4; i++)
                #pragma unroll
                for (int j = 0; j < 4; j++) acc[i][j] += a[i]*w[j];
        }
        __syncthreads();
    }
    int ti = tid & 15, tj = tid >> 4;
    #pragma unroll
    for (int i = 0; i < 4; i++) {
        int m = m0 + tj*4 + i;
        float4 v = make_float4(acc[i][0], acc[i][1], acc[i][2], acc[i][3]);
        *(float4*)&Out[(size_t)m*O + o0 + ti*4] = v;
    }
}

// Out[M][O] = A[M][Kd] * W[O][ldw]^T  (128x128 tile, 8x8 micro; big GEMM)
__global__ void k_gemm128(const float* __restrict__ A, const float* __restrict__ W,
                          float* __restrict__ Out, int O, int Kd, int ldw) {
    int m0 = blockIdx.y*128, o0 = blockIdx.x*128;
    __shared__ float As[8][132];
    __shared__ float Ws[8][132];
    int tid = threadIdx.x;
    float acc[8][8];
    #pragma unroll
    for (int i = 0; i < 8; i++)
        #pragma unroll
        for (int j = 0; j < 8; j++) acc[i][j] = 0.f;

    int lr = tid & 127;
    int lk = (tid >> 7) * 4;

    for (int k0 = 0; k0 < Kd; k0 += 8) {
        #pragma unroll
        for (int q = 0; q < 4; q++) {
            int kk = k0 + lk + q;
            As[lk+q][lr] = (kk < Kd) ? A[(size_t)(m0+lr)*Kd + kk] : 0.f;
            Ws[lk+q][lr] = (kk < Kd) ? W[(size_t)(o0+lr)*ldw + kk] : 0.f;
        }
        __syncthreads();
        int ti = tid & 15, tj = tid >> 4;
        #pragma unroll
        for (int k = 0; k < 8; k++) {
            float a[8], w[8];
            #pragma unroll
            for (int u = 0; u < 8; u++) { a[u] = As[k][tj*8+u]; w[u] = Ws[k][ti*8+u]; }
            #pragma unroll
            for (int i = 0; i < 8; i++)
                #pragma unroll
                for (int j = 0; j < 8; j++) acc[i][j] += a[i]*w[j];
        }
        __syncthreads();
    }
    int ti = tid & 15, tj = tid >> 4;
    #pragma unroll
    for (int i = 0; i < 8; i++) {
        int m = m0 + tj*8 + i;
        float* orow = &Out[(size_t)m*O + o0 + ti*8];
        float4 v0 = make_float4(acc[i][0], acc[i][1], acc[i][2], acc[i][3]);
        float4 v1 = make_float4(acc[i][4], acc[i][5], acc[i][6], acc[i][7]);
        *(float4*)&orow[0] = v0;
        *(float4*)&orow[4] = v1;
    }
}

// per (b,n): pre[o] = v[o] + max_k u[idx_k][o]; partial per-channel sum/sumsq
__global__ void k_gather(int O, float* __restrict__ pre) {
    int bn = blockIdx.x;
    int b = bn >> 12;
    __shared__ int nb[KNN];
    if (threadIdx.x < KNN) nb[threadIdx.x] = g_idx[bn*KNN + threadIdx.x];
    __syncthreads();
    int o = threadIdx.x;
    float vv = g_v[(size_t)bn*O + o];
    float mx = -3.4e38f, s = 0.f, ss = 0.f;
    #pragma unroll
    for (int k = 0; k < KNN; k++) {
        float h = g_u[((size_t)(b*NPTS + nb[k]))*O + o] + vv;
        mx = fmaxf(mx, h); s += h; ss += h*h;
    }
    pre[(size_t)bn*O + o] = mx;
    g_ps [(size_t)bn*O + o] = s;
    g_pss[(size_t)bn*O + o] = ss;
}

// deterministic reduction of partials -> g_sums/g_sumsq
__global__ void k_redstats(int nPart, int O) {
    int o = blockIdx.x, tid = threadIdx.x;
    float s = 0.f, ss = 0.f;
    for (int i = tid; i < nPart; i += 256) {
        s  += g_ps [(size_t)i*O + o];
        ss += g_pss[(size_t)i*O + o];
    }
    __shared__ float rs[256], rss[256];
    rs[tid] = s; rss[tid] = ss;
    __syncthreads();
    for (int st = 128; st > 0; st >>= 1) {
        if (tid < st) { rs[tid] += rs[tid+st]; rss[tid] += rss[tid+st]; }
        __syncthreads();
    }
    if (tid == 0) { g_sums[o] = rs[0]; g_sumsq[o] = rss[0]; }
}

// in-place affine-BN + leaky on max-pooled features
__global__ void k_finalize(const float* __restrict__ g, const float* __restrict__ bp,
                           float* __restrict__ buf, int O, float invCnt) {
    int i = blockIdx.x*blockDim.x + threadIdx.x;
    if (i >= BN_*O) return;
    int o = i % O;
    float mean = g_sums[o]*invCnt;
    float var  = g_sumsq[o]*invCnt - mean*mean;
    float sc = g[o]*rsqrtf(var + EPSV);
    float sh = bp[o] - mean*sc;
    float y = sc*buf[i] + sh;
    buf[i] = (y > 0.f) ? y : SLOPE*y;
}

__global__ void k_concat() {
    int i = blockIdx.x*blockDim.x + threadIdx.x;
    if (i >= BN_*512) return;
    int m = i / 512, c = i % 512;
    float v;
    if (c < 64)       v = g_x1[(size_t)m*64  + c];
    else if (c < 128) v = g_x2[(size_t)m*64  + c-64];
    else if (c < 256) v = g_x3[(size_t)m*128 + c-128];
    else              v = g_x4[(size_t)m*256 + c-256];
    g_cat[i] = v;
}

// partial per-channel stats of g_h (8192 x 1024): 256 blocks x 32 rows
__global__ void k_hstats() {
    int r0 = blockIdx.x*32;
    float s[4] = {0,0,0,0}, ss[4] = {0,0,0,0};
    for (int r = 0; r < 32; r++) {
        const float* row = &g_h[(size_t)(r0+r)*1024];
        #pragma unroll
        for (int q = 0; q < 4; q++) {
            float v = row[threadIdx.x + q*256];
            s[q] += v; ss[q] += v*v;
        }
    }
    #pragma unroll
    for (int q = 0; q < 4; q++) {
        g_ps [(size_t)blockIdx.x*1024 + threadIdx.x + q*256] = s[q];
        g_pss[(size_t)blockIdx.x*1024 + threadIdx.x + q*256] = ss[q];
    }
}

// BN + leaky + transpose: out[b][o][n]
__global__ void k_out(const float* __restrict__ g5, const float* __restrict__ b5,
                      float* __restrict__ out) {
    __shared__ float t[32][33];
    int b = blockIdx.z;
    int n0 = blockIdx.x*32, o0 = blockIdx.y*32;
    for (int dy = threadIdx.y; dy < 32; dy += 8) {
        int n = n0 + dy;
        t[dy][threadIdx.x] = g_h[(size_t)(b*NPTS + n)*1024 + o0 + threadIdx.x];
    }
    __syncthreads();
    const float invCnt = 1.f/8192.f;
    for (int dy = threadIdx.y; dy < 32; dy += 8) {
        int o = o0 + dy, n = n0 + threadIdx.x;
        float mean = g_sums[o]*invCnt;
        float var  = g_sumsq[o]*invCnt - mean*mean;
        float sc = g5[o]*rsqrtf(var + EPSV);
        float sh = b5[o] - mean*sc;
        float hv = t[threadIdx.x][dy];
        float y = sc*hv + sh;
        out[((size_t)b*1024 + o)*NPTS + n] = (y > 0.f) ? y : SLOPE*y;
    }
}

// ---------------- host launch ----------------

static void run_layer(const float* F, int C, const float* W, const float* g,
                      const float* bp, int O, float* outbuf,
                      float* p_u, float* p_v, float* p_wdiff) {
    k_sqnorm<<<(BN_+255)/256, 256>>>(F, C);
    k_dist128<<<dim3(NPTS/128, NPTS/128, BATCH), 256>>>(F, C);
    k_topk<<<BN_, 256>>>();
    k_wdiff<<<(O*C + 255)/256, 256>>>(W, O, C);
    k_gemm<<<dim3(O/64, BN_/64), 256>>>(F, W,       p_u, O, C, 2*C);  // u = Wa * x
    k_gemm<<<dim3(O/64, BN_/64), 256>>>(F, p_wdiff, p_v, O, C, C);    // v = (Wb-Wa)*x
    k_gather<<<BN_, O>>>(O, outbuf);
    k_redstats<<<O, 256>>>(BN_, O);
    k_finalize<<<(BN_*O + 255)/256, 256>>>(g, bp, outbuf, O, 1.f/CNT_EDGE);
}

extern "C" void kernel_launch(void* const* d_in, const int* in_sizes, int n_in,
                              void* d_out, int out_size) {
    const float* x  = (const float*)d_in[0];
    const float* W1 = (const float*)d_in[1];
    const float* g1 = (const float*)d_in[2];
    const float* b1 = (const float*)d_in[3];
    const float* W2 = (const float*)d_in[4];
    const float* g2 = (const float*)d_in[5];
    const float* b2 = (const float*)d_in[6];
    const float* W3 = (const float*)d_in[7];
    const float* g3 = (const float*)d_in[8];
    const float* b3 = (const float*)d_in[9];
    const float* W4 = (const float*)d_in[10];
    const float* g4 = (const float*)d_in[11];
    const float* b4 = (const float*)d_in[12];
    const float* W5 = (const float*)d_in[13];
    const float* g5 = (const float*)d_in[14];
    const float* b5 = (const float*)d_in[15];
    float* out = (float*)d_out;

    float *p_xb, *p_x1, *p_x2, *p_x3, *p_x4, *p_u, *p_v, *p_wdiff, *p_cat, *p_h;
    cudaGetSymbolAddress((void**)&p_xb,    g_xb);
    cudaGetSymbolAddress((void**)&p_x1,    g_x1);
    cudaGetSymbolAddress((void**)&p_x2,    g_x2);
    cudaGetSymbolAddress((void**)&p_x3,    g_x3);
    cudaGetSymbolAddress((void**)&p_x4,    g_x4);
    cudaGetSymbolAddress((void**)&p_u,     g_u);
    cudaGetSymbolAddress((void**)&p_v,     g_v);
    cudaGetSymbolAddress((void**)&p_wdiff, g_wdiff);
    cudaGetSymbolAddress((void**)&p_cat,   g_cat);
    cudaGetSymbolAddress((void**)&p_h,     g_h);

    k_transpose_x<<<(BN_+255)/256, 256>>>(x);

    run_layer(p_xb, 3,   W1, g1, b1, 64,  p_x1, p_u, p_v, p_wdiff);
    run_layer(p_x1, 64,  W2, g2, b2, 64,  p_x2, p_u, p_v, p_wdiff);
    run_layer(p_x2, 64,  W3, g3, b3, 128, p_x3, p_u, p_v, p_wdiff);
    run_layer(p_x3, 128, W4, g4, b4, 256, p_x4, p_u, p_v, p_wdiff);

    k_concat<<<(BN_*512 + 255)/256, 256>>>();
    k_gemm128<<<dim3(1024/128, BN_/128), 256>>>(p_cat, W5, p_h, 1024, 512, 512);
    k_hstats<<<256, 256>>>();
    k_redstats<<<1024, 256>>>(256, 1024);
    k_out<<<dim3(NPTS/32, 1024/32, BATCH), dim3(32, 8)>>>(g5, b5, out);
}

// round 4
// speedup vs baseline: 2.2950x; 1.5686x over previous
#include <cuda_runtime.h>
#include <cstdio>

#define BATCH 2
#define NPTS  4096
#define KNN   20
#define BN_   (BATCH*NPTS)        // 8192
#define CNT_EDGE (float)(BATCH*NPTS*KNN)   // 163840
#define EPSV 1e-5f
#define SLOPE 0.2f
#define TOPK_CAP 1024

// ---------------- static scratch (no runtime alloc allowed) ----------------
__device__ float g_xb[BN_*3];
__device__ float g_x1[BN_*64];
__device__ float g_x2[BN_*64];
__device__ float g_x3[BN_*128];
__device__ float g_x4[BN_*256];
__device__ float g_sq[BN_];
__device__ float g_D[(size_t)BATCH*NPTS*NPTS];   // 134MB distance scratch
__device__ int   g_idx[BN_*KNN];
__device__ float g_u[BN_*256];
__device__ float g_v[BN_*256];
__device__ float g_wdiff[256*256];
__device__ float g_cat[BN_*512];
__device__ float g_h[(size_t)BN_*1024];
__device__ float g_ps [(size_t)BN_*256];  // partial sums
__device__ float g_pss[(size_t)BN_*256];  // partial sumsq
__device__ float g_sums[1024];
__device__ float g_sumsq[1024];

// ---------------- kernels ----------------

// x (B,3,N) -> g_xb (B,N,3)
__global__ void k_transpose_x(const float* __restrict__ x) {
    int i = blockIdx.x*blockDim.x + threadIdx.x;
    if (i >= BN_) return;
    int b = i / NPTS, n = i % NPTS;
    #pragma unroll
    for (int c = 0; c < 3; c++)
        g_xb[(size_t)i*3 + c] = x[((size_t)b*3 + c)*NPTS + n];
}

// squared norms per row
__global__ void k_sqnorm(const float* __restrict__ F, int C) {
    int i = blockIdx.x*blockDim.x + threadIdx.x;
    if (i >= BN_) return;
    const float* r = F + (size_t)i*C;
    float s = 0.f;
    for (int c = 0; c < C; c++) s += r[c]*r[c];
    g_sq[i] = s;
}

// D[b][n][m] = 2*<x_n,x_m> - ||x_n||^2 - ||x_m||^2
// Symmetric: only tiles bx >= by computed; off-diagonal tiles mirrored via
// smem-staged transpose. 128x128 tile, 8x8 micro, double-buffered smem.
__global__ void k_dist_sym(const float* __restrict__ F, int C) {
    int bx = blockIdx.x, by = blockIdx.y;
    if (bx < by) return;
    int b = blockIdx.z;
    const float* Fb = F + (size_t)b*NPTS*C;
    int m0 = bx*128, n0 = by*128;

    __shared__ float As[2][8][132];
    __shared__ float Bs[2][8][132];
    __shared__ float tr[16][132];

    int tid = threadIdx.x;
    int lr = tid & 127;          // row within tile
    int lk4 = (tid >> 7) * 4;    // 0 or 4

    float acc[8][8];
    #pragma unroll
    for (int i = 0; i < 8; i++)
        #pragma unroll
        for (int j = 0; j < 8; j++) acc[i][j] = 0.f;

    int nIter = (C + 7) / 8;
    bool vec = (C % 8 == 0);

    // prologue load (buffer 0)
    if (vec) {
        float4 va = *(const float4*)&Fb[(size_t)(n0+lr)*C + lk4];
        float4 vb = *(const float4*)&Fb[(size_t)(m0+lr)*C + lk4];
        As[0][lk4+0][lr] = va.x; As[0][lk4+1][lr] = va.y;
        As[0][lk4+2][lr] = va.z; As[0][lk4+3][lr] = va.w;
        Bs[0][lk4+0][lr] = vb.x; Bs[0][lk4+1][lr] = vb.y;
        Bs[0][lk4+2][lr] = vb.z; Bs[0][lk4+3][lr] = vb.w;
    } else {
        #pragma unroll
        for (int q = 0; q < 4; q++) {
            int cc = lk4 + q;
            As[0][lk4+q][lr] = (cc < C) ? Fb[(size_t)(n0+lr)*C + cc] : 0.f;
            Bs[0][lk4+q][lr] = (cc < C) ? Fb[(size_t)(m0+lr)*C + cc] : 0.f;
        }
    }
    __syncthreads();

    int ti = tid & 15, tj = tid >> 4;   // ti -> m (fast), tj -> n
    for (int it = 0; it < nIter; it++) {
        int cur = it & 1, nxt = cur ^ 1;
        if (it + 1 < nIter) {
            int c0 = (it + 1) * 8;
            float4 va = *(const float4*)&Fb[(size_t)(n0+lr)*C + c0 + lk4];
            float4 vb = *(const float4*)&Fb[(size_t)(m0+lr)*C + c0 + lk4];
            As[nxt][lk4+0][lr] = va.x; As[nxt][lk4+1][lr] = va.y;
            As[nxt][lk4+2][lr] = va.z; As[nxt][lk4+3][lr] = va.w;
            Bs[nxt][lk4+0][lr] = vb.x; Bs[nxt][lk4+1][lr] = vb.y;
            Bs[nxt][lk4+2][lr] = vb.z; Bs[nxt][lk4+3][lr] = vb.w;
        }
        #pragma unroll
        for (int k = 0; k < 8; k++) {
            float a[8], bv[8];
            #pragma unroll
            for (int u = 0; u < 8; u++) { a[u] = As[cur][k][tj*8+u]; bv[u] = Bs[cur][k][ti*8+u]; }
            #pragma unroll
            for (int i = 0; i < 8; i++)
                #pragma unroll
                for (int j = 0; j < 8; j++) acc[i][j] += a[i]*bv[j];
        }
        __syncthreads();
    }

    // finalize distances in-register
    float sqm[8];
    #pragma unroll
    for (int j = 0; j < 8; j++) sqm[j] = g_sq[b*NPTS + m0 + ti*8 + j];
    #pragma unroll
    for (int i = 0; i < 8; i++) {
        float sqn = g_sq[b*NPTS + n0 + tj*8 + i];
        #pragma unroll
        for (int j = 0; j < 8; j++)
            acc[i][j] = 2.f*acc[i][j] - sqn - sqm[j];
    }

    // write normal tile: D[n][m]
    #pragma unroll
    for (int i = 0; i < 8; i++) {
        int n = n0 + tj*8 + i;
        float* orow = &g_D[((size_t)b*NPTS + n)*NPTS + m0 + ti*8];
        float4 v0 = make_float4(acc[i][0], acc[i][1], acc[i][2], acc[i][3]);
        float4 v1 = make_float4(acc[i][4], acc[i][5], acc[i][6], acc[i][7]);
        *(float4*)&orow[0] = v0;
        *(float4*)&orow[4] = v1;
    }

    // mirror: D[m][n] for off-diagonal tiles, staged through smem (coalesced)
    if (bx > by) {
        for (int cc = 0; cc < 8; cc++) {
            __syncthreads();
            if ((ti >> 1) == cc) {
                int rbase = (ti & 1) * 8;
                #pragma unroll
                for (int j = 0; j < 8; j++)
                    #pragma unroll
                    for (int i = 0; i < 8; i++)
                        tr[rbase + j][tj*8 + i] = acc[i][j];
            }
            __syncthreads();
            int rr = tid >> 4;           // 0..15
            int c0w = (tid & 15) * 8;    // 0..120
            int m = m0 + cc*16 + rr;
            float* dst = &g_D[((size_t)b*NPTS + m)*NPTS + n0 + c0w];
            float4 w0 = *(float4*)&tr[rr][c0w];
            float4 w1 = *(float4*)&tr[rr][c0w + 4];
            *(float4*)&dst[0] = w0;
            *(float4*)&dst[4] = w1;
        }
    }
}

__device__ __forceinline__ unsigned f2ord(float f) {
    unsigned u = __float_as_uint(f);
    return (u & 0x80000000u) ? ~u : (u | 0x80000000u);
}

// top-20 (largest values, tie -> lowest index) per distance row.
// Radix-select: single global pass, 11-bit histogram, candidate ranking.
__global__ void k_topk() {
    __shared__ unsigned hist[2048];
    __shared__ unsigned tsum[256];
    __shared__ int sh_bin, sh_above, ccnt;
    __shared__ unsigned long long cand[TOPK_CAP];

    int bn = blockIdx.x;
    int tid = threadIdx.x;
    const float4* rowv = (const float4*)&g_D[(size_t)bn*NPTS];

    for (int i = tid; i < 2048; i += 256) hist[i] = 0;
    if (tid == 0) ccnt = 0;
    __syncthreads();

    // load 16 values/thread, compute ordered keys, histogram top-11 bits
    unsigned ord[16];
    #pragma unroll
    for (int q = 0; q < 4; q++) {
        float4 v = rowv[tid + q*256];
        ord[q*4+0] = f2ord(v.x);
        ord[q*4+1] = f2ord(v.y);
        ord[q*4+2] = f2ord(v.z);
        ord[q*4+3] = f2ord(v.w);
    }
    #pragma unroll
    for (int q = 0; q < 16; q++) atomicAdd(&hist[ord[q] >> 21], 1u);
    __syncthreads();

    // per-thread sum over its 8 bins, then suffix-scan across threads
    unsigned s_local = 0;
    #pragma unroll
    for (int j = 0; j < 8; j++) s_local += hist[tid*8 + j];
    tsum[tid] = s_local;
    __syncthreads();
    for (int off = 1; off < 256; off <<= 1) {
        unsigned add = (tid + off < 256) ? tsum[tid + off] : 0u;
        __syncthreads();
        tsum[tid] += add;
        __syncthreads();
    }
    // tsum[tid] = sum over bins of threads >= tid
    unsigned cum = tsum[tid] - s_local;   // count strictly above this thread's bin range
    for (int j = 7; j >= 0; j--) {
        unsigned c = hist[tid*8 + j];
        if (cum < KNN && cum + c >= KNN) { sh_bin = tid*8 + j; sh_above = (int)cum; }
        cum += c;
    }
    __syncthreads();

    int thr = sh_bin;
    // collect candidates: all elements with bin >= threshold bin
    #pragma unroll
    for (int q = 0; q < 16; q++) {
        if ((int)(ord[q] >> 21) >= thr) {
            int idx = 4*(tid + (q >> 2)*256) + (q & 3);
            int p = atomicAdd(&ccnt, 1);
            if (p < TOPK_CAP)
                cand[p] = ((unsigned long long)ord[q] << 32) | (unsigned)(NPTS - 1 - idx);
        }
    }
    __syncthreads();

    int T = ccnt;
    if (T <= TOPK_CAP) {
        // rank candidates; keys are unique (index embedded) -> deterministic
        for (int i = tid; i < T; i += 256) {
            unsigned long long ki = cand[i];
            int r = 0;
            for (int j = 0; j < T; j++) r += (cand[j] > ki);
            if (r < KNN) {
                int idx = (NPTS - 1) - (int)(unsigned)(ki & 0xFFFFFFFFull);
                g_idx[bn*KNN + r] = idx;
            }
        }
    } else {
        // fallback (degenerate): iterative in-register selection, always correct
        __shared__ unsigned long long rb[256];
        unsigned mask = 0xFFFFu;
        for (int it = 0; it < KNN; it++) {
            unsigned long long best = 0ull;
            #pragma unroll
            for (int q = 0; q < 16; q++) {
                if ((mask >> q) & 1u) {
                    int idx = 4*(tid + (q >> 2)*256) + (q & 3);
                    unsigned long long k = ((unsigned long long)ord[q] << 32)
                                         | (unsigned)(NPTS - 1 - idx);
                    if (k > best) best = k;
                }
            }
            rb[tid] = best;
            __syncthreads();
            for (int st = 128; st > 0; st >>= 1) {
                if (tid < st && rb[tid + st] > rb[tid]) rb[tid] = rb[tid + st];
                __syncthreads();
            }
            unsigned long long win = rb[0];
            if (tid == 0)
                g_idx[bn*KNN + it] = (NPTS - 1) - (int)(unsigned)(win & 0xFFFFFFFFull);
            // owner clears its bit
            #pragma unroll
            for (int q = 0; q < 16; q++) {
                if ((mask >> q) & 1u) {
                    int idx = 4*(tid + (q >> 2)*256) + (q & 3);
                    unsigned long long k = ((unsigned long long)ord[q] << 32)
                                         | (unsigned)(NPTS - 1 - idx);
                    if (k == win) mask &= ~(1u << q);
                }
            }
            __syncthreads();
        }
    }
}

// wdiff[o][c] = W[o][C+c] - W[o][c]   (W is O x 2C)
__global__ void k_wdiff(const float* __restrict__ W, int O, int C) {
    int i = blockIdx.x*blockDim.x + threadIdx.x;
    if (i >= O*C) return;
    int o = i / C, c = i % C;
    g_wdiff[i] = W[(size_t)o*2*C + C + c] - W[(size_t)o*2*C + c];
}

// Out[M][O] = A[M][Kd] * W[O][ldw]^T  (64x64 tile; used for small point GEMMs)
__global__ void k_gemm(const float* __restrict__ A, const float* __restrict__ W,
                       float* __restrict__ Out, int O, int Kd, int ldw) {
    int m0 = blockIdx.y*64, o0 = blockIdx.x*64;
    __shared__ float As[16][68];
    __shared__ float Ws[16][68];
    int tid = threadIdx.x;
    float acc[4][4];
    #pragma unroll
    for (int i = 0; i < 4; i++)
        #pragma unroll
        for (int j = 0; j < 4; j++) acc[i][j] = 0.f;

    for (int k0 = 0; k0 < Kd; k0 += 16) {
        int r = tid >> 4, c = tid & 15;
        #pragma unroll
        for (int it = 0; it < 4; it++) {
            int row = r + it*16;
            int kk = k0 + c;
            As[c][row] = (kk < Kd) ? A[(size_t)(m0+row)*Kd + kk] : 0.f;
            Ws[c][row] = (kk < Kd) ? W[(size_t)(o0+row)*ldw + kk] : 0.f;
        }
        __syncthreads();
        int ti = tid & 15, tj = tid >> 4;
        #pragma unroll
        for (int k = 0; k < 16; k++) {
            float a[4], w[4];
            #pragma unroll
            for (int u = 0; u < 4; u++) { a[u] = As[k][tj*4+u]; w[u] = Ws[k][ti*4+u]; }
            #pragma unroll
            for (int i = 0; i < 4; i++)
                #pragma unroll
                for (int j = 0; j < 4; j++) acc[i][j] += a[i]*w[j];
        }
        __syncthreads();
    }
    int ti = tid & 15, tj = tid >> 4;
    #pragma unroll
    for (int i = 0; i < 4; i++) {
        int m = m0 + tj*4 + i;
        float4 v = make_float4(acc[i][0], acc[i][1], acc[i][2], acc[i][3]);
        *(float4*)&Out[(size_t)m*O + o0 + ti*4] = v;
    }
}

// Out[M][O] = A[M][Kd] * W[O][Kd]^T  (128x128 tile, 8x8 micro, double-buffered)
// Requires Kd % 8 == 0, ldw % 4 == 0 (used only for the final 512-K GEMM).
__global__ void k_gemm128(const float* __restrict__ A, const float* __restrict__ W,
                          float* __restrict__ Out, int O, int Kd, int ldw) {
    int m0 = blockIdx.y*128, o0 = blockIdx.x*128;
    __shared__ float As[2][8][132];
    __shared__ float Ws[2][8][132];
    int tid = threadIdx.x;
    int lr = tid & 127;
    int lk4 = (tid >> 7) * 4;

    float acc[8][8];
    #pragma unroll
    for (int i = 0; i < 8; i++)
        #pragma unroll
        for (int j = 0; j < 8; j++) acc[i][j] = 0.f;

    int nIter = Kd / 8;

    {
        float4 va = *(const float4*)&A[(size_t)(m0+lr)*Kd + lk4];
        float4 vw = *(const float4*)&W[(size_t)(o0+lr)*ldw + lk4];
        As[0][lk4+0][lr] = va.x; As[0][lk4+1][lr] = va.y;
        As[0][lk4+2][lr] = va.z; As[0][lk4+3][lr] = va.w;
        Ws[0][lk4+0][lr] = vw.x; Ws[0][lk4+1][lr] = vw.y;
        Ws[0][lk4+2][lr] = vw.z; Ws[0][lk4+3][lr] = vw.w;
    }
    __syncthreads();

    int ti = tid & 15, tj = tid >> 4;
    for (int it = 0; it < nIter; it++) {
        int cur = it & 1, nxt = cur ^ 1;
        if (it + 1 < nIter) {
            int k0 = (it + 1) * 8;
            float4 va = *(const float4*)&A[(size_t)(m0+lr)*Kd + k0 + lk4];
            float4 vw = *(const float4*)&W[(size_t)(o0+lr)*ldw + k0 + lk4];
            As[nxt][lk4+0][lr] = va.x; As[nxt][lk4+1][lr] = va.y;
            As[nxt][lk4+2][lr] = va.z; As[nxt][lk4+3][lr] = va.w;
            Ws[nxt][lk4+0][lr] = vw.x; Ws[nxt][lk4+1][lr] = vw.y;
            Ws[nxt][lk4+2][lr] = vw.z; Ws[nxt][lk4+3][lr] = vw.w;
        }
        #pragma unroll
        for (int k = 0; k < 8; k++) {
            float a[8], w[8];
            #pragma unroll
            for (int u = 0; u < 8; u++) { a[u] = As[cur][k][tj*8+u]; w[u] = Ws[cur][k][ti*8+u]; }
            #pragma unroll
            for (int i = 0; i < 8; i++)
                #pragma unroll
                for (int j = 0; j < 8; j++) acc[i][j] += a[i]*w[j];
        }
        __syncthreads();
    }

    #pragma unroll
    for (int i = 0; i < 8; i++) {
        int m = m0 + tj*8 + i;
        float* orow = &Out[(size_t)m*O + o0 + ti*8];
        float4 v0 = make_float4(acc[i][0], acc[i][1], acc[i][2], acc[i][3]);
        float4 v1 = make_float4(acc[i][4], acc[i][5], acc[i][6], acc[i][7]);
        *(float4*)&orow[0] = v0;
        *(float4*)&orow[4] = v1;
    }
}

// per (b,n): pre[o] = v[o] + max_k u[idx_k][o]; partial per-channel sum/sumsq
__global__ void k_gather(int O, float* __restrict__ pre) {
    int bn = blockIdx.x;
    int b = bn >> 12;
    __shared__ int nb[KNN];
    if (threadIdx.x < KNN) nb[threadIdx.x] = g_idx[bn*KNN + threadIdx.x];
    __syncthreads();
    int o = threadIdx.x;
    float vv = g_v[(size_t)bn*O + o];
    float mx = -3.4e38f, s = 0.f, ss = 0.f;
    #pragma unroll
    for (int k = 0; k < KNN; k++) {
        float h = g_u[((size_t)(b*NPTS + nb[k]))*O + o] + vv;
        mx = fmaxf(mx, h); s += h; ss += h*h;
    }
    pre[(size_t)bn*O + o] = mx;
    g_ps [(size_t)bn*O + o] = s;
    g_pss[(size_t)bn*O + o] = ss;
}

// deterministic reduction of partials -> g_sums/g_sumsq
__global__ void k_redstats(int nPart, int O) {
    int o = blockIdx.x, tid = threadIdx.x;
    float s = 0.f, ss = 0.f;
    for (int i = tid; i < nPart; i += 256) {
        s  += g_ps [(size_t)i*O + o];
        ss += g_pss[(size_t)i*O + o];
    }
    __shared__ float rs[256], rss[256];
    rs[tid] = s; rss[tid] = ss;
    __syncthreads();
    for (int st = 128; st > 0; st >>= 1) {
        if (tid < st) { rs[tid] += rs[tid+st]; rss[tid] += rss[tid+st]; }
        __syncthreads();
    }
    if (tid == 0) { g_sums[o] = rs[0]; g_sumsq[o] = rss[0]; }
}

// in-place affine-BN + leaky on max-pooled features
__global__ void k_finalize(const float* __restrict__ g, const float* __restrict__ bp,
                           float* __restrict__ buf, int O, float invCnt) {
    int i = blockIdx.x*blockDim.x + threadIdx.x;
    if (i >= BN_*O) return;
    int o = i % O;
    float mean = g_sums[o]*invCnt;
    float var  = g_sumsq[o]*invCnt - mean*mean;
    float sc = g[o]*rsqrtf(var + EPSV);
    float sh = bp[o] - mean*sc;
    float y = sc*buf[i] + sh;
    buf[i] = (y > 0.f) ? y : SLOPE*y;
}

__global__ void k_concat() {
    int i = blockIdx.x*blockDim.x + threadIdx.x;
    if (i >= BN_*512) return;
    int m = i / 512, c = i % 512;
    float v;
    if (c < 64)       v = g_x1[(size_t)m*64  + c];
    else if (c < 128) v = g_x2[(size_t)m*64  + c-64];
    else if (c < 256) v = g_x3[(size_t)m*128 + c-128];
    else              v = g_x4[(size_t)m*256 + c-256];
    g_cat[i] = v;
}

// partial per-channel stats of g_h (8192 x 1024): 256 blocks x 32 rows
__global__ void k_hstats() {
    int r0 = blockIdx.x*32;
    float s[4] = {0,0,0,0}, ss[4] = {0,0,0,0};
    for (int r = 0; r < 32; r++) {
        const float* row = &g_h[(size_t)(r0+r)*1024];
        #pragma unroll
        for (int q = 0; q < 4; q++) {
            float v = row[threadIdx.x + q*256];
            s[q] += v; ss[q] += v*v;
        }
    }
    #pragma unroll
    for (int q = 0; q < 4; q++) {
        g_ps [(size_t)blockIdx.x*1024 + threadIdx.x + q*256] = s[q];
        g_pss[(size_t)blockIdx.x*1024 + threadIdx.x + q*256] = ss[q];
    }
}

// BN + leaky + transpose: out[b][o][n]
__global__ void k_out(const float* __restrict__ g5, const float* __restrict__ b5,
                      float* __restrict__ out) {
    __shared__ float t[32][33];
    int b = blockIdx.z;
    int n0 = blockIdx.x*32, o0 = blockIdx.y*32;
    for (int dy = threadIdx.y; dy < 32; dy += 8) {
        int n = n0 + dy;
        t[dy][threadIdx.x] = g_h[(size_t)(b*NPTS + n)*1024 + o0 + threadIdx.x];
    }
    __syncthreads();
    const float invCnt = 1.f/8192.f;
    for (int dy = threadIdx.y; dy < 32; dy += 8) {
        int o = o0 + dy, n = n0 + threadIdx.x;
        float mean = g_sums[o]*invCnt;
        float var  = g_sumsq[o]*invCnt - mean*mean;
        float sc = g5[o]*rsqrtf(var + EPSV);
        float sh = b5[o] - mean*sc;
        float hv = t[threadIdx.x][dy];
        float y = sc*hv + sh;
        out[((size_t)b*1024 + o)*NPTS + n] = (y > 0.f) ? y : SLOPE*y;
    }
}

// ---------------- host launch ----------------

static void run_layer(const float* F, int C, const float* W, const float* g,
                      const float* bp, int O, float* outbuf,
                      float* p_u, float* p_v, float* p_wdiff) {
    k_sqnorm<<<(BN_+255)/256, 256>>>(F, C);
    k_dist_sym<<<dim3(NPTS/128, NPTS/128, BATCH), 256>>>(F, C);
    k_topk<<<BN_, 256>>>();
    k_wdiff<<<(O*C + 255)/256, 256>>>(W, O, C);
    k_gemm<<<dim3(O/64, BN_/64), 256>>>(F, W,       p_u, O, C, 2*C);  // u = Wa * x
    k_gemm<<<dim3(O/64, BN_/64), 256>>>(F, p_wdiff, p_v, O, C, C);    // v = (Wb-Wa)*x
    k_gather<<<BN_, O>>>(O, outbuf);
    k_redstats<<<O, 256>>>(BN_, O);
    k_finalize<<<(BN_*O + 255)/256, 256>>>(g, bp, outbuf, O, 1.f/CNT_EDGE);
}

extern "C" void kernel_launch(void* const* d_in, const int* in_sizes, int n_in,
                              void* d_out, int out_size) {
    const float* x  = (const float*)d_in[0];
    const float* W1 = (const float*)d_in[1];
    const float* g1 = (const float*)d_in[2];
    const float* b1 = (const float*)d_in[3];
    const float* W2 = (const float*)d_in[4];
    const float* g2 = (const float*)d_in[5];
    const float* b2 = (const float*)d_in[6];
    const float* W3 = (const float*)d_in[7];
    const float* g3 = (const float*)d_in[8];
    const float* b3 = (const float*)d_in[9];
    const float* W4 = (const float*)d_in[10];
    const float* g4 = (const float*)d_in[11];
    const float* b4 = (const float*)d_in[12];
    const float* W5 = (const float*)d_in[13];
    const float* g5 = (const float*)d_in[14];
    const float* b5 = (const float*)d_in[15];
    float* out = (float*)d_out;

    float *p_xb, *p_x1, *p_x2, *p_x3, *p_x4, *p_u, *p_v, *p_wdiff, *p_cat, *p_h;
    cudaGetSymbolAddress((void**)&p_xb,    g_xb);
    cudaGetSymbolAddress((void**)&p_x1,    g_x1);
    cudaGetSymbolAddress((void**)&p_x2,    g_x2);
    cudaGetSymbolAddress((void**)&p_x3,    g_x3);
    cudaGetSymbolAddress((void**)&p_x4,    g_x4);
    cudaGetSymbolAddress((void**)&p_u,     g_u);
    cudaGetSymbolAddress((void**)&p_v,     g_v);
    cudaGetSymbolAddress((void**)&p_wdiff, g_wdiff);
    cudaGetSymbolAddress((void**)&p_cat,   g_cat);
    cudaGetSymbolAddress((void**)&p_h,     g_h);

    k_transpose_x<<<(BN_+255)/256, 256>>>(x);

    run_layer(p_xb, 3,   W1, g1, b1, 64,  p_x1, p_u, p_v, p_wdiff);
    run_layer(p_x1, 64,  W2, g2, b2, 64,  p_x2, p_u, p_v, p_wdiff);
    run_layer(p_x2, 64,  W3, g3, b3, 128, p_x3, p_u, p_v, p_wdiff);
    run_layer(p_x3, 128, W4, g4, b4, 256, p_x4, p_u, p_v, p_wdiff);

    k_concat<<<(BN_*512 + 255)/256, 256>>>();
    k_gemm128<<<dim3(1024/128, BN_/128), 256>>>(p_cat, W5, p_h, 1024, 512, 512);
    k_hstats<<<256, 256>>>();
    k_redstats<<<1024, 256>>>(256, 1024);
    k_out<<<dim3(NPTS/32, 1024/32, BATCH), dim3(32, 8)>>>(g5, b5, out);
}